// round 15
// baseline (speedup 1.0000x reference)
#include <cuda_runtime.h>
#include <cstdint>

// ---------------------------------------------------------------------------
// Encoder_35064113004946 — tf32 HMMA + ldmatrix + A-reuse conv + bucket CSR
//
// EdgeConv: cat[x_i,x_j-x_i]@W = x_i@Wt+(x_j-x_i)@Wb; fold C=A-B into weights:
//   Wcat' = [Wtop-Wbot | Wbot]  =>  GEMM0 emits [D|B], D=A-B.
//   out_d = max_s relu(D_d + b + B_s) = relu(D_d + b + max_s B_s)
//   Edges: fixed-cap(64) buckets via atomicAdd slot (max is order-invariant).
// Conv1d(k=5,pad=2)+ReLU+MaxPool(2): k-chunks of 16 input channels; A tile
//   staged ONCE per chunk in padded-seq SMEM (2 zero rows around each length-L
//   sequence); the 5 conv taps read row-shifted fragments from SMEM. Warp
//   tiles never straddle sequence boundaries, so tap shift = constant address
//   offset and boundary zeros are real SMEM zeros. bias+relu+pool in epilogue.
// GEMMs: mma.sync.m16n8k8 tf32, ldmatrix.x4 fragments, cp.async staging,
//   all inputs pre-rounded to tf32 at producers.
// ---------------------------------------------------------------------------

#define M0 32768
#define E0 262144
#define M1 16384
#define E1 131072
#define CAP 64

// scratch layout (4-byte words)
#define OFF_X0     0
#define SZ_X0      (M0 * 128)
#define OFF_AB0    (OFF_X0 + SZ_X0)
#define SZ_AB0     (M0 * 512)
#define OFF_OUT0   (OFF_AB0 + SZ_AB0)
#define SZ_OUT0    (M0 * 256)
#define OFF_X1     (OFF_OUT0 + SZ_OUT0)
#define SZ_X1      (M1 * 256)
#define OFF_AB1    (OFF_X1 + SZ_X1)
#define SZ_AB1     (M1 * 512)
#define OFF_OUT1   (OFF_AB1 + SZ_AB1)
#define SZ_OUT1    (M1 * 256)
#define OFF_WCAT0  (OFF_OUT1 + SZ_OUT1)
#define SZ_WCAT0   (512 * 128)
#define OFF_WCAT1  (OFF_WCAT0 + SZ_WCAT0)
#define SZ_WCAT1   (512 * 256)
#define OFF_WT0    (OFF_WCAT1 + SZ_WCAT1)
#define SZ_WT      (256 * 1280)
#define OFF_WT1    (OFF_WT0 + SZ_WT)
#define OFF_BKT0   (OFF_WT1 + SZ_WT)
#define OFF_BKT1   (OFF_BKT0 + M0 * CAP)
#define OFF_CNT0   (OFF_BKT1 + M1 * CAP)
#define OFF_CNT1   (OFF_CNT0 + M0)
#define SCRATCH_TOTAL (OFF_CNT1 + M1)

__device__ __align__(16) unsigned g_scratch[SCRATCH_TOTAL];

// ---------------------------------------------------------------------------
__device__ __forceinline__ float rndtf32(float x) {
    unsigned r;
    asm("cvt.rna.tf32.f32 %0, %1;" : "=r"(r) : "f"(x));
    return __uint_as_float(r);
}
__device__ __forceinline__ void mma_tf32(float* d, const unsigned* a, const unsigned* b) {
    asm volatile(
        "mma.sync.aligned.m16n8k8.row.col.f32.tf32.tf32.f32 "
        "{%0,%1,%2,%3}, {%4,%5,%6,%7}, {%8,%9}, {%0,%1,%2,%3};\n"
        : "+f"(d[0]), "+f"(d[1]), "+f"(d[2]), "+f"(d[3])
        : "r"(a[0]), "r"(a[1]), "r"(a[2]), "r"(a[3]), "r"(b[0]), "r"(b[1]));
}
__device__ __forceinline__ void ldsm4(unsigned* r, uint32_t addr) {
    asm volatile("ldmatrix.sync.aligned.m8n8.x4.shared.b16 {%0,%1,%2,%3}, [%4];"
                 : "=r"(r[0]), "=r"(r[1]), "=r"(r[2]), "=r"(r[3]) : "r"(addr));
}
__device__ __forceinline__ uint32_t smem_u32(const void* p) {
    uint32_t a;
    asm("{ .reg .u64 t; cvta.to.shared.u64 t, %1; cvt.u32.u64 %0, t; }"
        : "=r"(a) : "l"(p));
    return a;
}
__device__ __forceinline__ float4 max4(float4 a, float4 b) {
    return make_float4(fmaxf(a.x, b.x), fmaxf(a.y, b.y),
                       fmaxf(a.z, b.z), fmaxf(a.w, b.w));
}

// ---------------------------------------------------------------------------
__global__ void permute_in(const float* __restrict__ data, float* __restrict__ x0) {
    int idx = blockIdx.x * 256 + threadIdx.x;
    int f = idx & 127, node = idx >> 7;
    int t = node & 127, bn = node >> 7;
    int b = bn >> 5, n = bn & 31;
    x0[idx] = rndtf32(data[(((t * 8 + b) * 32 + n) << 7) + f]);
}

// ---------------------------------------------------------------------------
// Weights N-MAJOR [N][K] (tf32-rounded):
//  WcatT: row h of 512: h<256 -> Wtop-Wbot, else Wbot
//  WtT:   row o of 256, cols kk=k*256+i: Wc[o,i,k]
__global__ void prep_weights(const float* __restrict__ W0, const float* __restrict__ W1,
                             const float* __restrict__ Wc0, const float* __restrict__ Wc1,
                             float* __restrict__ WcT0, float* __restrict__ WcT1,
                             float* __restrict__ WtT0, float* __restrict__ WtT1) {
    int idx = blockIdx.x * 256 + threadIdx.x;
    if (idx < 65536) {
        int h = idx >> 7, f = idx & 127;
        WcT0[idx] = rndtf32((h < 256) ? W0[f * 256 + h] - W0[(128 + f) * 256 + h]
                                      : W0[(128 + f) * 256 + (h - 256)]);
        return;
    }
    idx -= 65536;
    if (idx < 131072) {
        int h = idx >> 8, i = idx & 255;
        WcT1[idx] = rndtf32((h < 256) ? W1[i * 256 + h] - W1[(256 + i) * 256 + h]
                                      : W1[(256 + i) * 256 + (h - 256)]);
        return;
    }
    idx -= 131072;
    if (idx < 327680) {
        int o = idx / 1280, kk = idx % 1280;
        int k = kk >> 8, i = kk & 255;
        WtT0[idx] = rndtf32(Wc0[(o * 256 + i) * 5 + k]);
        return;
    }
    idx -= 327680;
    if (idx < 327680) {
        int o = idx / 1280, kk = idx % 1280;
        int k = kk >> 8, i = kk & 255;
        WtT1[idx] = rndtf32(Wc1[(o * 256 + i) * 5 + k]);
    }
}

// ---------------------------------------------------------------------------
__global__ void zero_cnt(int* __restrict__ p) {
    p[blockIdx.x * 256 + threadIdx.x] = 0;
}

__global__ void fill_edges(const int* __restrict__ ei, int E,
                           int* __restrict__ cnt, int* __restrict__ bkt) {
    int e = blockIdx.x * 256 + threadIdx.x;
    if (e >= E) return;
    int dst = __ldg(ei + E + e);
    int slot = atomicAdd(cnt + dst, 1);
    if (slot < CAP) bkt[(size_t)dst * CAP + slot] = __ldg(ei + e);
}

// ---------------------------------------------------------------------------
__global__ void gather_max(const int* __restrict__ cnt, const int* __restrict__ bkt,
                           const float* __restrict__ AB, const float* __restrict__ bias,
                           float* __restrict__ out, int nodes) {
    int d = (blockIdx.x * 256 + threadIdx.x) >> 5;
    if (d >= nodes) return;
    int lane = threadIdx.x & 31;
    int n = __ldg(cnt + d);
    n = n < CAP ? n : CAP;
    float4* O = (float4*)(out + (size_t)d * 256);
    if (n == 0) {
        O[lane] = make_float4(0.f, 0.f, 0.f, 0.f);
        O[lane + 32] = make_float4(0.f, 0.f, 0.f, 0.f);
        return;
    }
    const int* bp = bkt + (size_t)d * CAP;
    const float NEG = -3.4e38f;
    float4 m0 = make_float4(NEG, NEG, NEG, NEG), m1 = m0;
    int e = 0;
    for (; e + 1 < n; e += 2) {
        int sa = __ldg(bp + e), sb = __ldg(bp + e + 1);
        const float4* Ba = (const float4*)(AB + (size_t)sa * 512 + 256);
        const float4* Bb = (const float4*)(AB + (size_t)sb * 512 + 256);
        m0 = max4(m0, max4(__ldg(Ba + lane), __ldg(Bb + lane)));
        m1 = max4(m1, max4(__ldg(Ba + lane + 32), __ldg(Bb + lane + 32)));
    }
    if (e < n) {
        int sa = __ldg(bp + e);
        const float4* Ba = (const float4*)(AB + (size_t)sa * 512 + 256);
        m0 = max4(m0, __ldg(Ba + lane));
        m1 = max4(m1, __ldg(Ba + lane + 32));
    }
    const float4* D = (const float4*)(AB + (size_t)d * 512);
    float4 d0 = __ldg(D + lane), d1 = __ldg(D + lane + 32);
    float4 b0 = __ldg((const float4*)bias + lane), b1 = __ldg((const float4*)bias + lane + 32);
    O[lane] = make_float4(rndtf32(fmaxf(d0.x + b0.x + m0.x, 0.f)),
                          rndtf32(fmaxf(d0.y + b0.y + m0.y, 0.f)),
                          rndtf32(fmaxf(d0.z + b0.z + m0.z, 0.f)),
                          rndtf32(fmaxf(d0.w + b0.w + m0.w, 0.f)));
    O[lane + 32] = make_float4(rndtf32(fmaxf(d1.x + b1.x + m1.x, 0.f)),
                               rndtf32(fmaxf(d1.y + b1.y + m1.y, 0.f)),
                               rndtf32(fmaxf(d1.z + b1.z + m1.z, 0.f)),
                               rndtf32(fmaxf(d1.w + b1.w + m1.w, 0.f)));
}

// ---------------------------------------------------------------------------
// GEMM0: C[M,N] = A[M,K] @ BwT[N,K]^T. Block 128x128, 8 warps (32x64),
// 3-stage cp.async, ldmatrix fragments. (round-14 path, unchanged)
#define SROW_W 20
#define SA_SZ (128 * SROW_W)
#define GEMM_SMEM ((6 * SA_SZ) * 4)

__global__ __launch_bounds__(256, 2)
void gemm0(const float* __restrict__ A, const float* __restrict__ BwT,
           float* __restrict__ C, int N, int K, int astride) {
    extern __shared__ float smem[];
    float* sA = smem;
    float* sB = smem + 3 * SA_SZ;
    int tid = threadIdx.x;
    int lane = tid & 31, wid = tid >> 5;
    int wm = wid & 3, wn = wid >> 2;
    int gid = lane >> 2, tg = lane & 3;
    int bm = blockIdx.y * 128, bn = blockIdx.x * 128;
    float acc[2][8][4] = {};

    int lq = lane >> 3, lr = lane & 7;
    uint32_t smem_base = smem_u32(smem);
    uint32_t aOff = ((wm * 32 + (lq & 1) * 8 + lr) * SROW_W + (lq >> 1) * 4) * 4;
    uint32_t bOff = ((wn * 64 + (lq >> 1) * 8 + lr) * SROW_W + (lq & 1) * 4) * 4;

    auto stage = [&](int buf, int k0) {
        float* bA = sA + buf * SA_SZ;
        float* bB = sB + buf * SA_SZ;
#pragma unroll
        for (int h = 0; h < 2; h++) {
            int q = tid + h * 256;
            int r = q >> 2, quad = q & 3;
            uint32_t dst = smem_u32(bA + r * SROW_W + quad * 4);
            const float* src = A + (size_t)(bm + r) * astride + k0 + quad * 4;
            asm volatile("cp.async.ca.shared.global [%0], [%1], 16;"
                         :: "r"(dst), "l"(src) : "memory");
        }
#pragma unroll
        for (int h = 0; h < 2; h++) {
            int q = tid + h * 256;
            int r = q >> 2, quad = q & 3;
            uint32_t dst = smem_u32(bB + r * SROW_W + quad * 4);
            const float* src = BwT + (size_t)(bn + r) * K + k0 + quad * 4;
            asm volatile("cp.async.ca.shared.global [%0], [%1], 16;"
                         :: "r"(dst), "l"(src) : "memory");
        }
        asm volatile("cp.async.commit_group;" ::: "memory");
    };

    int KT = K >> 4;
    stage(0, 0);
    stage(1, 16);
    for (int kt = 0; kt < KT; kt++) {
        if (kt + 1 < KT)
            asm volatile("cp.async.wait_group 1;" ::: "memory");
        else
            asm volatile("cp.async.wait_group 0;" ::: "memory");
        __syncthreads();
        int buf = kt % 3;
        uint32_t aAddr = smem_base + (buf * SA_SZ) * 4 + aOff;
        uint32_t bAddr = smem_base + (3 * SA_SZ + buf * SA_SZ) * 4 + bOff;
#pragma unroll
        for (int kk = 0; kk < 16; kk += 8) {
            unsigned a[2][4], b[8][2];
            ldsm4(a[0], aAddr + kk * 4);
            ldsm4(a[1], aAddr + 16 * SROW_W * 4 + kk * 4);
#pragma unroll
            for (int p = 0; p < 4; p++) {
                unsigned t4[4];
                ldsm4(t4, bAddr + p * 16 * SROW_W * 4 + kk * 4);
                b[2 * p][0] = t4[0]; b[2 * p][1] = t4[1];
                b[2 * p + 1][0] = t4[2]; b[2 * p + 1][1] = t4[3];
            }
#pragma unroll
            for (int mi = 0; mi < 2; mi++)
#pragma unroll
                for (int ni = 0; ni < 8; ni++)
                    mma_tf32(acc[mi][ni], a[mi], b[ni]);
        }
        if (kt + 2 < KT) stage((kt + 2) % 3, (kt + 2) << 4);
    }

#pragma unroll
    for (int mi = 0; mi < 2; mi++) {
        int r0 = bm + wm * 32 + mi * 16 + gid;
#pragma unroll
        for (int ni = 0; ni < 8; ni++) {
            int c0 = bn + wn * 64 + ni * 8 + tg * 2;
            *(float2*)(C + (size_t)r0 * N + c0) = make_float2(acc[mi][ni][0], acc[mi][ni][1]);
            *(float2*)(C + (size_t)(r0 + 8) * N + c0) = make_float2(acc[mi][ni][2], acc[mi][ni][3]);
        }
    }
}

// ---------------------------------------------------------------------------
// Conv GEMM: Y = pool(relu(conv1d(X) + bias)). X:[M,256], WtT:[256][1280]
// (kk = k*256+i), Y:[M/2, 256]. Block 128(M) x 128(N), 8 warps (32x64).
// 16 chunks of 16 input channels; A staged ONCE per chunk in padded-seq SMEM
// (rows per seq s of length L: [2 zero][L data][2 zero]); taps sh=0..4 read
// fragment rows +sh. B chunk: [128 n][5 taps x 16], stride 84.
#define CAROW_W 20
#define CA_SZ (136 * CAROW_W)     // max padded rows (L=64 -> 136)
#define CBROW_W 84
#define CB_SZ (128 * CBROW_W)
#define CONV_SMEM ((2 * CA_SZ + 2 * CB_SZ) * 4)

template <int L, int FIN>
__global__ __launch_bounds__(256, 2)
void convpool(const float* __restrict__ X, const float* __restrict__ WtT,
              const float* __restrict__ bias, float* __restrict__ Y) {
    extern __shared__ float smem[];
    float* sA = smem;                    // [2][CA_SZ]
    float* sB = smem + 2 * CA_SZ;        // [2][CB_SZ]
    constexpr int SEQP = L + 4;
    constexpr int NSEQ = 128 / L;
    constexpr int PADR = 128 + 4 * NSEQ;
    int tid = threadIdx.x;
    int lane = tid & 31, wid = tid >> 5;
    int wm = wid & 3, wn = wid >> 2;
    int gid = lane >> 2, tg = lane & 3;
    int bm = blockIdx.y * 128, bn = blockIdx.x * 128;
    float acc[2][8][4] = {};

    int lq = lane >> 3, lr = lane & 7;
    uint32_t smem_base = smem_u32(smem);
    int swarp = (wm * 32) / L;           // seq index of this warp's tile
    uint32_t aOff = ((wm * 32 + 4 * swarp + (lq & 1) * 8 + lr) * CAROW_W + (lq >> 1) * 4) * 4;
    uint32_t bOff = ((wn * 64 + (lq >> 1) * 8 + lr) * CBROW_W + (lq & 1) * 4) * 4;

    auto stage = [&](int buf, int i0) {
        float* bA = sA + buf * CA_SZ;
        float* bB = sB + buf * CB_SZ;
        // A: PADR rows x 16 cols (4x 16B chunks per row)
#pragma unroll
        for (int h = 0; h < 3; h++) {
            int q = tid + h * 256;
            if (q < PADR * 4) {
                int p = q >> 2, cq = q & 3;
                int s = p / SEQP, off = p % SEQP;
                int srow = bm, sz = 0;
                if (off >= 2 && off < L + 2) { srow = bm + s * L + off - 2; sz = 16; }
                uint32_t dst = smem_u32(bA + p * CAROW_W + cq * 4);
                const float* src = X + (size_t)srow * 256 + i0 + cq * 4;
                asm volatile("cp.async.ca.shared.global [%0], [%1], 16, %2;"
                             :: "r"(dst), "l"(src), "r"(sz) : "memory");
            }
        }
        // B: 128 rows x 80 cols (20x 16B chunks per row)
#pragma unroll
        for (int h = 0; h < 10; h++) {
            int q = tid + h * 256;
            int r = q / 20, c = q % 20;
            int sh = c >> 2, cq = c & 3;
            uint32_t dst = smem_u32(bB + r * CBROW_W + c * 4);
            const float* src = WtT + (size_t)(bn + r) * 1280 + sh * 256 + i0 + cq * 4;
            asm volatile("cp.async.ca.shared.global [%0], [%1], 16;"
                         :: "r"(dst), "l"(src) : "memory");
        }
        asm volatile("cp.async.commit_group;" ::: "memory");
    };

    stage(0, 0);
    for (int ct = 0; ct < 16; ct++) {
        if (ct + 1 < 16) {
            stage((ct + 1) & 1, (ct + 1) * 16);
            asm volatile("cp.async.wait_group 1;" ::: "memory");
        } else {
            asm volatile("cp.async.wait_group 0;" ::: "memory");
        }
        __syncthreads();
        int buf = ct & 1;
        uint32_t aAddr = smem_base + (buf * CA_SZ) * 4 + aOff;
        uint32_t bAddr = smem_base + (2 * CA_SZ + buf * CB_SZ) * 4 + bOff;
#pragma unroll
        for (int sh = 0; sh < 5; sh++) {
            uint32_t aSh = aAddr + sh * CAROW_W * 4;
            uint32_t bSh = bAddr + sh * 16 * 4;
#pragma unroll
            for (int kk = 0; kk < 16; kk += 8) {
                unsigned a[2][4], b[8][2];
                ldsm4(a[0], aSh + kk * 4);
                ldsm4(a[1], aSh + 16 * CAROW_W * 4 + kk * 4);
#pragma unroll
                for (int p = 0; p < 4; p++) {
                    unsigned t4[4];
                    ldsm4(t4, bSh + p * 16 * CBROW_W * 4 + kk * 4);
                    b[2 * p][0] = t4[0]; b[2 * p][1] = t4[1];
                    b[2 * p + 1][0] = t4[2]; b[2 * p + 1][1] = t4[3];
                }
#pragma unroll
                for (int mi = 0; mi < 2; mi++)
#pragma unroll
                    for (int ni = 0; ni < 8; ni++)
                        mma_tf32(acc[mi][ni], a[mi], b[ni]);
            }
        }
        __syncthreads();
    }

    // epilogue: +bias, relu, maxpool(2); partner row gid^1 lives in lane^4
    bool wr = (gid & 1) == 0;
#pragma unroll
    for (int mi = 0; mi < 2; mi++) {
        int rbase = bm + wm * 32 + mi * 16 + gid;
#pragma unroll
        for (int ni = 0; ni < 8; ni++) {
            int c0 = bn + wn * 64 + ni * 8 + tg * 2;
            float b0 = bias[c0], b1 = bias[c0 + 1];
            float u0 = fmaxf(acc[mi][ni][0] + b0, 0.f);
            float u1 = fmaxf(acc[mi][ni][1] + b1, 0.f);
            float u2 = fmaxf(acc[mi][ni][2] + b0, 0.f);
            float u3 = fmaxf(acc[mi][ni][3] + b1, 0.f);
            float p0 = fmaxf(u0, __shfl_xor_sync(0xffffffffu, u0, 4));
            float p1 = fmaxf(u1, __shfl_xor_sync(0xffffffffu, u1, 4));
            float p2 = fmaxf(u2, __shfl_xor_sync(0xffffffffu, u2, 4));
            float p3 = fmaxf(u3, __shfl_xor_sync(0xffffffffu, u3, 4));
            if constexpr (!FIN) {
                p0 = rndtf32(p0); p1 = rndtf32(p1);
                p2 = rndtf32(p2); p3 = rndtf32(p3);
            }
            if (wr) {
                *(float2*)(Y + (size_t)(rbase >> 1) * 256 + c0) = make_float2(p0, p1);
                *(float2*)(Y + (size_t)((rbase + 8) >> 1) * 256 + c0) = make_float2(p2, p3);
            }
        }
    }
}

// ---------------------------------------------------------------------------
extern "C" void kernel_launch(void* const* d_in, const int* in_sizes, int n_in,
                              void* d_out, int out_size) {
    const float* data = (const float*)d_in[0];
    const int*   ei0  = (const int*)d_in[2];
    const int*   ei1  = (const int*)d_in[3];
    const float* W0   = (const float*)d_in[4];
    const float* b0   = (const float*)d_in[5];
    const float* Wc0  = (const float*)d_in[6];
    const float* bc0  = (const float*)d_in[7];
    const float* W1   = (const float*)d_in[8];
    const float* b1   = (const float*)d_in[9];
    const float* Wc1  = (const float*)d_in[10];
    const float* bc1  = (const float*)d_in[11];
    float* out = (float*)d_out;

    void* sp = nullptr;
    cudaGetSymbolAddress(&sp, g_scratch);
    float* S     = (float*)sp;
    float* x0    = S + OFF_X0;
    float* AB0   = S + OFF_AB0;
    float* out0  = S + OFF_OUT0;
    float* x1    = S + OFF_X1;
    float* AB1   = S + OFF_AB1;
    float* out1  = S + OFF_OUT1;
    float* WcT0  = S + OFF_WCAT0;
    float* WcT1  = S + OFF_WCAT1;
    float* WtT0  = S + OFF_WT0;
    float* WtT1  = S + OFF_WT1;
    int* bkt0 = (int*)(S + OFF_BKT0);
    int* bkt1 = (int*)(S + OFF_BKT1);
    int* cnt0 = (int*)(S + OFF_CNT0);
    int* cnt1 = (int*)(S + OFF_CNT1);

    static bool attr_done = false;
    if (!attr_done) {
        cudaFuncSetAttribute(gemm0, cudaFuncAttributeMaxDynamicSharedMemorySize, GEMM_SMEM);
        cudaFuncSetAttribute(convpool<128, 0>, cudaFuncAttributeMaxDynamicSharedMemorySize, CONV_SMEM);
        cudaFuncSetAttribute(convpool<64, 1>, cudaFuncAttributeMaxDynamicSharedMemorySize, CONV_SMEM);
        attr_done = true;
    }

    prep_weights<<<3328, 256>>>(W0, W1, Wc0, Wc1, WcT0, WcT1, WtT0, WtT1);
    permute_in<<<(M0 * 128) / 256, 256>>>(data, x0);
    zero_cnt<<<(M0 + M1) / 256, 256>>>(cnt0);   // cnt0,cnt1 contiguous

    fill_edges<<<E0 / 256, 256>>>(ei0, E0, cnt0, bkt0);
    fill_edges<<<E1 / 256, 256>>>(ei1, E1, cnt1, bkt1);

    // layer 0
    gemm0<<<dim3(4, M0 / 128), 256, GEMM_SMEM>>>(x0, WcT0, AB0, 512, 128, 128);
    gather_max<<<M0 / 8, 256>>>(cnt0, bkt0, AB0, b0, out0, M0);
    convpool<128, 0><<<dim3(2, M0 / 128), 256, CONV_SMEM>>>(out0, WtT0, bc0, x1);

    // layer 1
    gemm0<<<dim3(4, M1 / 128), 256, GEMM_SMEM>>>(x1, WcT1, AB1, 512, 256, 256);
    gather_max<<<M1 / 8, 256>>>(cnt1, bkt1, AB1, b1, out1, M1);
    convpool<64, 1><<<dim3(2, M1 / 128), 256, CONV_SMEM>>>(out1, WtT1, bc1, out);
}

// round 17
// speedup vs baseline: 1.7456x; 1.7456x over previous
#include <cuda_runtime.h>
#include <cuda_fp16.h>
#include <cstdint>

// ---------------------------------------------------------------------------
// Encoder_35064113004946 — fp16 HMMA (m16n8k16) + ldmatrix + bucket CSR
//
// EdgeConv: cat[x_i,x_j-x_i]@W = x_i@Wt+(x_j-x_i)@Wb; fold C=A-B into weights:
//   Wcat' = [Wtop-Wbot | Wbot]  =>  GEMM0 emits [D|B], D=A-B.
//   out_d = max_s relu(D_d + b + B_s) = relu(D_d + b + max_s B_s)
//   Edges: fixed-cap(64) buckets via atomicAdd slot (max is order-invariant).
//   Gather: warp-per-dst, fp16 rows, exact __hmax2 max; decode in fp32.
// Conv1d(k=5,pad=2)+ReLU+MaxPool(2): 8 chunks of 32 input channels; A staged
//   once per chunk in padded-seq SMEM; 5 taps = row-shifted fragments.
//   bias+relu+pool fused in epilogue (fp32), output fp16 (final layer fp32).
// GEMMs: mma.sync.m16n8k16.f32.f16.f16.f32 — fp16 keeps tf32's 10-bit
//   mantissa, halves MMA+LDSM counts and all memory traffic. fp32 accum.
// ---------------------------------------------------------------------------

#define M0 32768
#define E0 262144
#define M1 16384
#define E1 131072
#define CAP 64

// scratch layout (4-byte words); fp16 buffers count halves/2
#define OFF_X0     0
#define SZ_X0      (M0 * 64)
#define OFF_AB0    (OFF_X0 + SZ_X0)
#define SZ_AB0     (M0 * 256)
#define OFF_OUT0   (OFF_AB0 + SZ_AB0)
#define SZ_OUT0    (M0 * 128)
#define OFF_X1     (OFF_OUT0 + SZ_OUT0)
#define SZ_X1      (M1 * 128)
#define OFF_AB1    (OFF_X1 + SZ_X1)
#define SZ_AB1     (M1 * 256)
#define OFF_OUT1   (OFF_AB1 + SZ_AB1)
#define SZ_OUT1    (M1 * 128)
#define OFF_WCT0   (OFF_OUT1 + SZ_OUT1)
#define SZ_WCT0    (512 * 128 / 2)
#define OFF_WCT1   (OFF_WCT0 + SZ_WCT0)
#define SZ_WCT1    (512 * 256 / 2)
#define OFF_WTT0   (OFF_WCT1 + SZ_WCT1)
#define SZ_WTT     (256 * 1280 / 2)
#define OFF_WTT1   (OFF_WTT0 + SZ_WTT)
#define OFF_BKT0   (OFF_WTT1 + SZ_WTT)
#define OFF_BKT1   (OFF_BKT0 + M0 * CAP)
#define OFF_CNT0   (OFF_BKT1 + M1 * CAP)
#define OFF_CNT1   (OFF_CNT0 + M0)
#define SCRATCH_TOTAL (OFF_CNT1 + M1)

__device__ __align__(16) unsigned g_scratch[SCRATCH_TOTAL];

// ---------------------------------------------------------------------------
__device__ __forceinline__ void mma_f16(float* d, const unsigned* a, const unsigned* b) {
    asm volatile(
        "mma.sync.aligned.m16n8k16.row.col.f32.f16.f16.f32 "
        "{%0,%1,%2,%3}, {%4,%5,%6,%7}, {%8,%9}, {%0,%1,%2,%3};\n"
        : "+f"(d[0]), "+f"(d[1]), "+f"(d[2]), "+f"(d[3])
        : "r"(a[0]), "r"(a[1]), "r"(a[2]), "r"(a[3]), "r"(b[0]), "r"(b[1]));
}
__device__ __forceinline__ void ldsm4(unsigned* r, uint32_t addr) {
    asm volatile("ldmatrix.sync.aligned.m8n8.x4.shared.b16 {%0,%1,%2,%3}, [%4];"
                 : "=r"(r[0]), "=r"(r[1]), "=r"(r[2]), "=r"(r[3]) : "r"(addr));
}
__device__ __forceinline__ uint32_t smem_u32(const void* p) {
    uint32_t a;
    asm("{ .reg .u64 t; cvta.to.shared.u64 t, %1; cvt.u32.u64 %0, t; }"
        : "=r"(a) : "l"(p));
    return a;
}
__device__ __forceinline__ unsigned hmax2u(unsigned a, unsigned b) {
    __half2 r = __hmax2(*(__half2*)&a, *(__half2*)&b);
    return *(unsigned*)&r;
}
__device__ __forceinline__ uint4 hmax8(uint4 a, uint4 b) {
    return make_uint4(hmax2u(a.x, b.x), hmax2u(a.y, b.y),
                      hmax2u(a.z, b.z), hmax2u(a.w, b.w));
}

// ---------------------------------------------------------------------------
// input permute: data[T,B,N,F] -> x0[(b*32+n)*128 + t, f] as fp16 (half2)
__global__ void permute_in(const float* __restrict__ data, __half2* __restrict__ x0) {
    int idx = blockIdx.x * 256 + threadIdx.x;      // over M0*64 half2
    int f2 = idx & 63, node = idx >> 6;
    int t = node & 127, bn = node >> 7;
    int b = bn >> 5, n = bn & 31;
    float2 v = *(const float2*)(data + (((t * 8 + b) * 32 + n) << 7) + f2 * 2);
    x0[idx] = __floats2half2_rn(v.x, v.y);
}

// ---------------------------------------------------------------------------
// Weights N-MAJOR [N][K] fp16:
//  WcT: row h of 512: h<256 -> Wtop-Wbot, else Wbot
//  WtT: row o of 256, cols kk=k*256+i: Wc[o,i,k]
__global__ void prep_weights(const float* __restrict__ W0, const float* __restrict__ W1,
                             const float* __restrict__ Wc0, const float* __restrict__ Wc1,
                             __half* __restrict__ WcT0, __half* __restrict__ WcT1,
                             __half* __restrict__ WtT0, __half* __restrict__ WtT1) {
    int idx = blockIdx.x * 256 + threadIdx.x;
    if (idx < 65536) {
        int h = idx >> 7, f = idx & 127;
        WcT0[idx] = __float2half_rn((h < 256) ? W0[f * 256 + h] - W0[(128 + f) * 256 + h]
                                              : W0[(128 + f) * 256 + (h - 256)]);
        return;
    }
    idx -= 65536;
    if (idx < 131072) {
        int h = idx >> 8, i = idx & 255;
        WcT1[idx] = __float2half_rn((h < 256) ? W1[i * 256 + h] - W1[(256 + i) * 256 + h]
                                              : W1[(256 + i) * 256 + (h - 256)]);
        return;
    }
    idx -= 131072;
    if (idx < 327680) {
        int o = idx / 1280, kk = idx % 1280;
        int k = kk >> 8, i = kk & 255;
        WtT0[idx] = __float2half_rn(Wc0[(o * 256 + i) * 5 + k]);
        return;
    }
    idx -= 327680;
    if (idx < 327680) {
        int o = idx / 1280, kk = idx % 1280;
        int k = kk >> 8, i = kk & 255;
        WtT1[idx] = __float2half_rn(Wc1[(o * 256 + i) * 5 + k]);
    }
}

// ---------------------------------------------------------------------------
__global__ void zero_cnt(int* __restrict__ p) {
    p[blockIdx.x * 256 + threadIdx.x] = 0;
}

__global__ void fill_edges(const int* __restrict__ ei, int E,
                           int* __restrict__ cnt, int* __restrict__ bkt) {
    int e = blockIdx.x * 256 + threadIdx.x;
    if (e >= E) return;
    int dst = __ldg(ei + E + e);
    int slot = atomicAdd(cnt + dst, 1);
    if (slot < CAP) bkt[(size_t)dst * CAP + slot] = __ldg(ei + e);
}

// ---------------------------------------------------------------------------
// warp-per-dst: out[d] = relu(D[d]+bias+max_s B[s]) -> fp16; 0 if empty.
// AB rows: 512 halves ([D(256) | B(256)]). Per lane: 8 channels (one uint4).
__global__ void gather_max(const int* __restrict__ cnt, const int* __restrict__ bkt,
                           const __half* __restrict__ AB, const float* __restrict__ bias,
                           __half* __restrict__ out, int nodes) {
    int d = (blockIdx.x * 256 + threadIdx.x) >> 5;
    if (d >= nodes) return;
    int lane = threadIdx.x & 31;
    uint4* O = (uint4*)(out + (size_t)d * 256) + lane;
    int n = __ldg(cnt + d);
    n = n < CAP ? n : CAP;
    if (n == 0) {
        *O = make_uint4(0, 0, 0, 0);
        return;
    }
    const int* bp = bkt + (size_t)d * CAP;
    uint4 m = make_uint4(0xFC00FC00u, 0xFC00FC00u, 0xFC00FC00u, 0xFC00FC00u); // -inf
    int e = 0;
    for (; e + 1 < n; e += 2) {
        int sa = __ldg(bp + e), sb = __ldg(bp + e + 1);
        uint4 va = __ldg((const uint4*)(AB + (size_t)sa * 512 + 256) + lane);
        uint4 vb = __ldg((const uint4*)(AB + (size_t)sb * 512 + 256) + lane);
        m = hmax8(m, hmax8(va, vb));
    }
    if (e < n) {
        int sa = __ldg(bp + e);
        m = hmax8(m, __ldg((const uint4*)(AB + (size_t)sa * 512 + 256) + lane));
    }
    uint4 dd = __ldg((const uint4*)(AB + (size_t)d * 512) + lane);
    float4 bb0 = __ldg((const float4*)bias + lane * 2);
    float4 bb1 = __ldg((const float4*)bias + lane * 2 + 1);
    float2 d0 = __half22float2(*(__half2*)&dd.x), m0 = __half22float2(*(__half2*)&m.x);
    float2 d1 = __half22float2(*(__half2*)&dd.y), m1 = __half22float2(*(__half2*)&m.y);
    float2 d2 = __half22float2(*(__half2*)&dd.z), m2 = __half22float2(*(__half2*)&m.z);
    float2 d3 = __half22float2(*(__half2*)&dd.w), m3 = __half22float2(*(__half2*)&m.w);
    __half2 o0 = __floats2half2_rn(fmaxf(d0.x + bb0.x + m0.x, 0.f), fmaxf(d0.y + bb0.y + m0.y, 0.f));
    __half2 o1 = __floats2half2_rn(fmaxf(d1.x + bb0.z + m1.x, 0.f), fmaxf(d1.y + bb0.w + m1.y, 0.f));
    __half2 o2 = __floats2half2_rn(fmaxf(d2.x + bb1.x + m2.x, 0.f), fmaxf(d2.y + bb1.y + m2.y, 0.f));
    __half2 o3 = __floats2half2_rn(fmaxf(d3.x + bb1.z + m3.x, 0.f), fmaxf(d3.y + bb1.w + m3.y, 0.f));
    *O = make_uint4(*(unsigned*)&o0, *(unsigned*)&o1, *(unsigned*)&o2, *(unsigned*)&o3);
}

// ---------------------------------------------------------------------------
// GEMM0: C[M,N] = A[M,K] @ BwT[N,K]^T, all fp16, fp32 accum, fp16 out.
// Block 128x128, 8 warps (32x64), k-chunk 32, 3-stage cp.async, ldmatrix.
// SMEM row stride 40 halves (80 B): 8-row LDSM hits 8 distinct bank quads.
#define SROW_H 40
#define SA_H (128 * SROW_H)
#define GEMM_SMEM (6 * SA_H * 2)

__global__ __launch_bounds__(256, 2)
void gemm0(const __half* __restrict__ A, const __half* __restrict__ BwT,
           __half* __restrict__ C, int N, int K, int astride) {
    extern __shared__ __half smh[];
    __half* sA = smh;                 // [3][128][40]
    __half* sB = smh + 3 * SA_H;      // [3][128][40]
    int tid = threadIdx.x;
    int lane = tid & 31, wid = tid >> 5;
    int wm = wid & 3, wn = wid >> 2;
    int gid = lane >> 2, tg = lane & 3;
    int bm = blockIdx.y * 128, bn = blockIdx.x * 128;
    float acc[2][8][4] = {};

    int lq = lane >> 3, lr = lane & 7;
    uint32_t smem_base = smem_u32(smh);
    // A x4: m0..m3 = [r0-7,k0-7][r8-15,k0-7][r0-7,k8-15][r8-15,k8-15]
    uint32_t aOff = ((wm * 32 + (lq & 1) * 8 + lr) * SROW_H + (lq >> 1) * 8) * 2;
    // B x4: [n0-7,k0-7][n0-7,k8-15][n8-15,k0-7][n8-15,k8-15]
    uint32_t bOff = ((wn * 64 + (lq >> 1) * 8 + lr) * SROW_H + (lq & 1) * 8) * 2;

    auto stage = [&](int buf, int k0) {
        __half* bA = sA + buf * SA_H;
        __half* bB = sB + buf * SA_H;
#pragma unroll
        for (int h = 0; h < 2; h++) {
            int q = tid + h * 256;                 // 512 chunks: 128 rows x 4
            int r = q >> 2, cq = q & 3;
            uint32_t dst = smem_u32(bA + r * SROW_H + cq * 8);
            const __half* src = A + (size_t)(bm + r) * astride + k0 + cq * 8;
            asm volatile("cp.async.ca.shared.global [%0], [%1], 16;"
                         :: "r"(dst), "l"(src) : "memory");
        }
#pragma unroll
        for (int h = 0; h < 2; h++) {
            int q = tid + h * 256;
            int r = q >> 2, cq = q & 3;
            uint32_t dst = smem_u32(bB + r * SROW_H + cq * 8);
            const __half* src = BwT + (size_t)(bn + r) * K + k0 + cq * 8;
            asm volatile("cp.async.ca.shared.global [%0], [%1], 16;"
                         :: "r"(dst), "l"(src) : "memory");
        }
        asm volatile("cp.async.commit_group;" ::: "memory");
    };

    int KT = K >> 5;                   // k-chunks of 32
    stage(0, 0);
    stage(1, 32);
    for (int kt = 0; kt < KT; kt++) {
        if (kt + 1 < KT)
            asm volatile("cp.async.wait_group 1;" ::: "memory");
        else
            asm volatile("cp.async.wait_group 0;" ::: "memory");
        __syncthreads();
        int buf = kt % 3;
        uint32_t aAddr = smem_base + buf * SA_H * 2 + aOff;
        uint32_t bAddr = smem_base + (3 * SA_H + buf * SA_H) * 2 + bOff;
#pragma unroll
        for (int kk = 0; kk < 32; kk += 16) {
            unsigned a[2][4], b[8][2];
            ldsm4(a[0], aAddr + kk * 2);
            ldsm4(a[1], aAddr + 16 * SROW_H * 2 + kk * 2);
#pragma unroll
            for (int p = 0; p < 4; p++) {
                unsigned t4[4];
                ldsm4(t4, bAddr + p * 16 * SROW_H * 2 + kk * 2);
                b[2 * p][0] = t4[0]; b[2 * p][1] = t4[1];
                b[2 * p + 1][0] = t4[2]; b[2 * p + 1][1] = t4[3];
            }
#pragma unroll
            for (int mi = 0; mi < 2; mi++)
#pragma unroll
                for (int ni = 0; ni < 8; ni++)
                    mma_f16(acc[mi][ni], a[mi], b[ni]);
        }
        if (kt + 2 < KT) stage((kt + 2) % 3, (kt + 2) << 5);
    }

#pragma unroll
    for (int mi = 0; mi < 2; mi++) {
        int r0 = bm + wm * 32 + mi * 16 + gid;
#pragma unroll
        for (int ni = 0; ni < 8; ni++) {
            int c0 = bn + wn * 64 + ni * 8 + tg * 2;
            *(__half2*)(C + (size_t)r0 * N + c0) = __floats2half2_rn(acc[mi][ni][0], acc[mi][ni][1]);
            *(__half2*)(C + (size_t)(r0 + 8) * N + c0) = __floats2half2_rn(acc[mi][ni][2], acc[mi][ni][3]);
        }
    }
}

// ---------------------------------------------------------------------------
// Conv GEMM: Y = pool(relu(conv1d(X)+bias)). X:[M,256] fp16, WtT:[256][1280]
// fp16 (kk=k*256+i). 8 chunks of 32 channels; A staged once per chunk in
// padded-seq SMEM; taps sh=0..4 = +sh row offset. FIN=0 -> Y fp16 [M/2,256];
// FIN=1 -> Y fp32 [M/2,256].
#define CAROW_H 40
#define CA_H (136 * CAROW_H)
#define CBROW_H 168
#define CB_H (128 * CBROW_H)
#define CONV_SMEM ((2 * CA_H + 2 * CB_H) * 2)

template <int L, int FIN>
__global__ __launch_bounds__(256, 2)
void convpool(const __half* __restrict__ X, const __half* __restrict__ WtT,
              const float* __restrict__ bias, void* __restrict__ Yv) {
    extern __shared__ __half smh[];
    __half* sA = smh;                 // [2][CA_H]
    __half* sB = smh + 2 * CA_H;      // [2][CB_H]
    constexpr int SEQP = L + 4;
    constexpr int PADR = 128 + 4 * (128 / L);
    int tid = threadIdx.x;
    int lane = tid & 31, wid = tid >> 5;
    int wm = wid & 3, wn = wid >> 2;
    int gid = lane >> 2, tg = lane & 3;
    int bm = blockIdx.y * 128, bn = blockIdx.x * 128;
    float acc[2][8][4] = {};

    int lq = lane >> 3, lr = lane & 7;
    uint32_t smem_base = smem_u32(smh);
    int swarp = (wm * 32) / L;
    uint32_t aOff = ((wm * 32 + 4 * swarp + (lq & 1) * 8 + lr) * CAROW_H + (lq >> 1) * 8) * 2;
    uint32_t bOff = ((wn * 64 + (lq >> 1) * 8 + lr) * CBROW_H + (lq & 1) * 8) * 2;

    auto stage = [&](int buf, int i0) {
        __half* bA = sA + buf * CA_H;
        __half* bB = sB + buf * CB_H;
        // A: PADR rows x 32 halves (4x 16B chunks per row), zfill pads
#pragma unroll
        for (int h = 0; h < 3; h++) {
            int q = tid + h * 256;
            if (q < PADR * 4) {
                int p = q >> 2, cq = q & 3;
                int s = p / SEQP, off = p % SEQP;
                int srow = bm, sz = 0;
                if (off >= 2 && off < L + 2) { srow = bm + s * L + off - 2; sz = 16; }
                uint32_t dst = smem_u32(bA + p * CAROW_H + cq * 8);
                const __half* src = X + (size_t)srow * 256 + i0 + cq * 8;
                asm volatile("cp.async.ca.shared.global [%0], [%1], 16, %2;"
                             :: "r"(dst), "l"(src), "r"(sz) : "memory");
            }
        }
        // B: 128 rows x 5 taps x 32 halves (20x 16B chunks per row)
#pragma unroll
        for (int h = 0; h < 10; h++) {
            int q = tid + h * 256;
            int r = q / 20, c = q % 20;
            int sh = c >> 2, cq = c & 3;
            uint32_t dst = smem_u32(bB + r * CBROW_H + c * 8);
            const __half* src = WtT + (size_t)(bn + r) * 1280 + sh * 256 + i0 + cq * 8;
            asm volatile("cp.async.ca.shared.global [%0], [%1], 16;"
                         :: "r"(dst), "l"(src) : "memory");
        }
        asm volatile("cp.async.commit_group;" ::: "memory");
    };

    stage(0, 0);
    for (int ct = 0; ct < 8; ct++) {
        if (ct + 1 < 8) {
            stage((ct + 1) & 1, (ct + 1) * 32);
            asm volatile("cp.async.wait_group 1;" ::: "memory");
        } else {
            asm volatile("cp.async.wait_group 0;" ::: "memory");
        }
        __syncthreads();
        int buf = ct & 1;
        uint32_t aAddr = smem_base + buf * CA_H * 2 + aOff;
        uint32_t bAddr = smem_base + (2 * CA_H + buf * CB_H) * 2 + bOff;
#pragma unroll
        for (int sh = 0; sh < 5; sh++) {
            uint32_t aSh = aAddr + sh * CAROW_H * 2;   // +sh rows
            uint32_t bSh = bAddr + sh * 32 * 2;        // tap block in row
#pragma unroll
            for (int kk = 0; kk < 32; kk += 16) {
                unsigned a[2][4], b[8][2];
                ldsm4(a[0], aSh + kk * 2);
                ldsm4(a[1], aSh + 16 * CAROW_H * 2 + kk * 2);
#pragma unroll
                for (int p = 0; p < 4; p++) {
                    unsigned t4[4];
                    ldsm4(t4, bSh + p * 16 * CBROW_H * 2 + kk * 2);
                    b[2 * p][0] = t4[0]; b[2 * p][1] = t4[1];
                    b[2 * p + 1][0] = t4[2]; b[2 * p + 1][1] = t4[3];
                }
#pragma unroll
                for (int mi = 0; mi < 2; mi++)
#pragma unroll
                    for (int ni = 0; ni < 8; ni++)
                        mma_f16(acc[mi][ni], a[mi], b[ni]);
            }
        }
        __syncthreads();
    }

    // epilogue: +bias, relu, maxpool(2); partner row gid^1 lives in lane^4
    bool wr = (gid & 1) == 0;
#pragma unroll
    for (int mi = 0; mi < 2; mi++) {
        int rbase = bm + wm * 32 + mi * 16 + gid;
#pragma unroll
        for (int ni = 0; ni < 8; ni++) {
            int c0 = bn + wn * 64 + ni * 8 + tg * 2;
            float b0 = bias[c0], b1 = bias[c0 + 1];
            float u0 = fmaxf(acc[mi][ni][0] + b0, 0.f);
            float u1 = fmaxf(acc[mi][ni][1] + b1, 0.f);
            float u2 = fmaxf(acc[mi][ni][2] + b0, 0.f);
            float u3 = fmaxf(acc[mi][ni][3] + b1, 0.f);
            float p0 = fmaxf(u0, __shfl_xor_sync(0xffffffffu, u0, 4));
            float p1 = fmaxf(u1, __shfl_xor_sync(0xffffffffu, u1, 4));
            float p2 = fmaxf(u2, __shfl_xor_sync(0xffffffffu, u2, 4));
            float p3 = fmaxf(u3, __shfl_xor_sync(0xffffffffu, u3, 4));
            if (wr) {
                if constexpr (FIN) {
                    float* Y = (float*)Yv;
                    *(float2*)(Y + (size_t)(rbase >> 1) * 256 + c0) = make_float2(p0, p1);
                    *(float2*)(Y + (size_t)((rbase + 8) >> 1) * 256 + c0) = make_float2(p2, p3);
                } else {
                    __half* Y = (__half*)Yv;
                    *(__half2*)(Y + (size_t)(rbase >> 1) * 256 + c0) = __floats2half2_rn(p0, p1);
                    *(__half2*)(Y + (size_t)((rbase + 8) >> 1) * 256 + c0) = __floats2half2_rn(p2, p3);
                }
            }
        }
    }
}

// ---------------------------------------------------------------------------
extern "C" void kernel_launch(void* const* d_in, const int* in_sizes, int n_in,
                              void* d_out, int out_size) {
    const float* data = (const float*)d_in[0];
    const int*   ei0  = (const int*)d_in[2];
    const int*   ei1  = (const int*)d_in[3];
    const float* W0   = (const float*)d_in[4];
    const float* b0   = (const float*)d_in[5];
    const float* Wc0  = (const float*)d_in[6];
    const float* bc0  = (const float*)d_in[7];
    const float* W1   = (const float*)d_in[8];
    const float* b1   = (const float*)d_in[9];
    const float* Wc1  = (const float*)d_in[10];
    const float* bc1  = (const float*)d_in[11];
    float* out = (float*)d_out;

    void* sp = nullptr;
    cudaGetSymbolAddress(&sp, g_scratch);
    unsigned* S = (unsigned*)sp;
    __half* x0   = (__half*)(S + OFF_X0);
    __half* AB0  = (__half*)(S + OFF_AB0);
    __half* out0 = (__half*)(S + OFF_OUT0);
    __half* x1   = (__half*)(S + OFF_X1);
    __half* AB1  = (__half*)(S + OFF_AB1);
    __half* out1 = (__half*)(S + OFF_OUT1);
    __half* WcT0 = (__half*)(S + OFF_WCT0);
    __half* WcT1 = (__half*)(S + OFF_WCT1);
    __half* WtT0 = (__half*)(S + OFF_WTT0);
    __half* WtT1 = (__half*)(S + OFF_WTT1);
    int* bkt0 = (int*)(S + OFF_BKT0);
    int* bkt1 = (int*)(S + OFF_BKT1);
    int* cnt0 = (int*)(S + OFF_CNT0);
    int* cnt1 = (int*)(S + OFF_CNT1);

    static bool attr_done = false;
    if (!attr_done) {
        cudaFuncSetAttribute(gemm0, cudaFuncAttributeMaxDynamicSharedMemorySize, GEMM_SMEM);
        cudaFuncSetAttribute(convpool<128, 0>, cudaFuncAttributeMaxDynamicSharedMemorySize, CONV_SMEM);
        cudaFuncSetAttribute(convpool<64, 1>, cudaFuncAttributeMaxDynamicSharedMemorySize, CONV_SMEM);
        attr_done = true;
    }

    prep_weights<<<3328, 256>>>(W0, W1, Wc0, Wc1, WcT0, WcT1, WtT0, WtT1);
    permute_in<<<(M0 * 64) / 256, 256>>>(data, (__half2*)x0);
    zero_cnt<<<(M0 + M1) / 256, 256>>>(cnt0);   // cnt0,cnt1 contiguous

    fill_edges<<<E0 / 256, 256>>>(ei0, E0, cnt0, bkt0);
    fill_edges<<<E1 / 256, 256>>>(ei1, E1, cnt1, bkt1);

    // layer 0
    gemm0<<<dim3(4, M0 / 128), 256, GEMM_SMEM>>>(x0, WcT0, AB0, 512, 128, 128);
    gather_max<<<M0 / 8, 256>>>(cnt0, bkt0, AB0, b0, out0, M0);
    convpool<128, 0><<<dim3(2, M0 / 128), 256, CONV_SMEM>>>(out0, WtT0, bc0, x1);

    // layer 1
    gemm0<<<dim3(4, M1 / 128), 256, GEMM_SMEM>>>(x1, WcT1, AB1, 512, 256, 256);
    gather_max<<<M1 / 8, 256>>>(cnt1, bkt1, AB1, b1, out1, M1);
    convpool<64, 1><<<dim3(2, M1 / 128), 256, CONV_SMEM>>>(out1, WtT1, bc1, out);
}